// round 6
// baseline (speedup 1.0000x reference)
#include <cuda_runtime.h>
#include <cuda_fp16.h>
#include <cstdint>

// ---------------- problem constants ----------------
#define BATCH   8
#define C2DIM   128
#define C3DIM   256
#define HDIM    28
#define WDIM    28
#define H3      14
#define W3      14
#define CDIM    384
#define NPATCH  6272
#define MBANK   30000
#define MBANK_PAD 30720             // 3 splits * 40 tiles * 256 rows

// ---------------- tiling ----------------
#define MSPLIT   3
#define TILE_M   128                // patches per CTA
#define TILE_N   256                // bank rows per CTA tile
#define NTILES   49                 // NPATCH / TILE_M
#define BTILES   40                 // bank tiles per split (40*256 = 10240)
#define CHUNKS   (BTILES * 6)       // k-chunks of 64 per split stream

#define ASTRIDE  392                // fp16 elems per A row (384 + 8 pad)
#define ABYTES   (128 * ASTRIDE * 2)    // 100352
#define BROWB    144                // bytes per B row (64 fp16 + 8 pad)
#define BBUF     (TILE_N * BROWB)   // 36864
#define NSTAGE   3
#define SM_TOTAL (ABYTES + NSTAGE * BBUF)   // 210944

#define NTHREADS 512

// ---------------- scratch ----------------
__device__ __align__(16) __half g_pat_hf[(size_t)NPATCH * CDIM];
__device__ __align__(16) __half g_bank_hf[(size_t)MBANK_PAD * CDIM];
__device__ float g_xsq[NPATCH];
__device__ float g_msq[MBANK_PAD];
__device__ float g_part[MSPLIT * NPATCH];

__device__ __forceinline__ uint32_t s2u(const void* p) {
    uint32_t r;
    asm("{ .reg .u64 t; cvta.to.shared.u64 t, %1; cvt.u32.u64 %0, t; }"
        : "=r"(r) : "l"(p));
    return r;
}

// ============================ prep kernels ============================
__global__ void embed_kernel(const float* __restrict__ f2,
                             const float* __restrict__ f3) {
    int idx = blockIdx.x * blockDim.x + threadIdx.x;
    if (idx >= NPATCH * CDIM) return;
    int n = idx / CDIM;
    int c = idx - n * CDIM;
    int b = n / (HDIM * WDIM);
    int hw = n - b * (HDIM * WDIM);
    int h = hw / WDIM;
    int w = hw - h * WDIM;

    float val;
    if (c < C2DIM) {
        val = f2[(((size_t)b * C2DIM + c) * HDIM + h) * WDIM + w];
    } else {
        int c3 = c - C2DIM;
        float sh = h * 0.5f - 0.25f;
        float sw = w * 0.5f - 0.25f;
        int h0 = (int)floorf(sh);
        int w0 = (int)floorf(sw);
        float th = sh - (float)h0;
        float tw = sw - (float)w0;
        int h0c = h0 < 0 ? 0 : h0;   int h1c = h0 + 1 > H3 - 1 ? H3 - 1 : h0 + 1;
        int w0c = w0 < 0 ? 0 : w0;   int w1c = w0 + 1 > W3 - 1 ? W3 - 1 : w0 + 1;
        const float* base = f3 + ((size_t)b * C3DIM + c3) * (H3 * W3);
        float v00 = base[h0c * W3 + w0c];
        float v01 = base[h0c * W3 + w1c];
        float v10 = base[h1c * W3 + w0c];
        float v11 = base[h1c * W3 + w1c];
        val = (1.f - th) * ((1.f - tw) * v00 + tw * v01)
            +        th  * ((1.f - tw) * v10 + tw * v11);
    }
    g_pat_hf[(size_t)n * CDIM + c] = __float2half_rn(val);
}

// bank fp32 -> fp16 (+ zero pad rows) + squared norm of rounded values
__global__ void bankcvt_kernel(const float* __restrict__ bank) {
    int warp = (blockIdx.x * blockDim.x + threadIdx.x) >> 5;
    int lane = threadIdx.x & 31;
    if (warp >= MBANK_PAD) return;
    uint32_t* dst = (uint32_t*)(g_bank_hf + (size_t)warp * CDIM);
    if (warp >= MBANK) {
        #pragma unroll
        for (int j = 0; j < CDIM / 64; ++j) dst[j * 32 + lane] = 0u;
        if (lane == 0) g_msq[warp] = __int_as_float(0x7f800000);
        return;
    }
    const float2* src = (const float2*)(bank + (size_t)warp * CDIM);
    float s = 0.f;
    #pragma unroll
    for (int j = 0; j < CDIM / 64; ++j) {
        float2 v = src[j * 32 + lane];
        __half2 hv = __float22half2_rn(v);
        dst[j * 32 + lane] = *(uint32_t*)&hv;
        float2 r = __half22float2(hv);
        s += r.x * r.x + r.y * r.y;
    }
    #pragma unroll
    for (int off = 16; off; off >>= 1) s += __shfl_xor_sync(0xffffffffu, s, off);
    if (lane == 0) g_msq[warp] = s;
}

__global__ void xsq_kernel() {
    int warp = (blockIdx.x * blockDim.x + threadIdx.x) >> 5;
    int lane = threadIdx.x & 31;
    if (warp >= NPATCH) return;
    const uint32_t* src = (const uint32_t*)(g_pat_hf + (size_t)warp * CDIM);
    float s = 0.f;
    #pragma unroll
    for (int j = 0; j < CDIM / 64; ++j) {
        uint32_t u = src[j * 32 + lane];
        float2 r = __half22float2(*(__half2*)&u);
        s += r.x * r.x + r.y * r.y;
    }
    #pragma unroll
    for (int off = 16; off; off >>= 1) s += __shfl_xor_sync(0xffffffffu, s, off);
    if (lane == 0) g_xsq[warp] = s;
}

// ============================ main GEMM+min kernel ============================
// 512 threads, 16 warps in 2(m) x 8(n); warp tile 64x32, mma.m16n8k16 f16 accum.
__global__ void __launch_bounds__(NTHREADS, 1) nn_kernel() {
    extern __shared__ __align__(1024) char smem[];
    char* Asm = smem;
    const int tid  = threadIdx.x;
    const int lane = tid & 31;
    const int wid  = tid >> 5;
    const int wm   = wid >> 3;      // 0..1
    const int wn   = wid & 7;       // 0..7
    const int n0   = blockIdx.x * TILE_M;
    const int split = blockIdx.y;
    const int mbase = split * (BTILES * TILE_N);

    const uint32_t aSm = s2u(smem);
    const uint32_t bSm = aSm + ABYTES;

    // ---- load A tile (128 x 384 fp16) into smem, stride 392 ----
    #pragma unroll
    for (int i = 0; i < 12; ++i) {
        int e = i * NTHREADS + tid;
        int r = e / 48, q = e - r * 48;
        uint4 v = *(const uint4*)(g_pat_hf + (size_t)(n0 + r) * CDIM + q * 8);
        *(uint4*)(Asm + r * (ASTRIDE * 2) + q * 16) = v;
    }

    // per-lane ldmatrix base addresses
    const uint32_t aBase = aSm +
        ((wm * 64 + (lane & 15)) * ASTRIDE + (lane >> 4) * 8) * 2;
    const int lq = lane >> 3;
    const int bn = (lane & 7) + ((lq >> 1) << 3);
    const int bk = (lq & 1) << 3;
    const uint32_t bBase = bSm + (wn * 32 + bn) * BROWB + bk * 2;

    float rowmin[4][2];
    #pragma unroll
    for (int i = 0; i < 4; ++i) {
        rowmin[i][0] = __int_as_float(0x7f800000);
        rowmin[i][1] = __int_as_float(0x7f800000);
    }

    // ---- chunk loader (cp.async, 256 rows x 64 k-cols fp16 = 32KB) ----
    auto load_chunk = [&](int cg) {
        int t  = cg / 6;
        int kc = cg - t * 6;
        int st = cg % NSTAGE;
        const char* src0 = (const char*)(g_bank_hf +
                           (size_t)(mbase + t * TILE_N) * CDIM + kc * 64);
        uint32_t dbase = bSm + (uint32_t)st * BBUF;
        #pragma unroll
        for (int i = 0; i < 4; ++i) {
            int e = i * NTHREADS + tid;
            int r = e >> 3, q = e & 7;
            uint32_t d = dbase + r * BROWB + q * 16;
            const char* s = src0 + (size_t)r * (CDIM * 2) + q * 16;
            asm volatile("cp.async.cg.shared.global [%0], [%1], 16;"
                         :: "r"(d), "l"(s));
        }
        asm volatile("cp.async.commit_group;");
    };

    load_chunk(0);
    load_chunk(1);
    __syncthreads();   // covers the A-tile stores

    int cg = 0;
    for (int t = 0; t < BTILES; ++t) {
        uint32_t acc[4][4][2];      // f16x2 accumulators
        #pragma unroll
        for (int mt = 0; mt < 4; ++mt)
            #pragma unroll
            for (int nt = 0; nt < 4; ++nt) {
                acc[mt][nt][0] = 0u; acc[mt][nt][1] = 0u;
            }

        #pragma unroll 1
        for (int j = 0; j < 6; ++j, ++cg) {
            asm volatile("cp.async.wait_group 1;");   // chunk cg resident
            __syncthreads();                          // all warps past chunk cg-1
            if (cg + 2 < CHUNKS) load_chunk(cg + 2);  // into stage (cg+2)%3

            const uint32_t bBuf = bBase + (uint32_t)(cg % NSTAGE) * BBUF;
            const uint32_t aCol = aBase + (j * 64) * 2;

            uint32_t a[2][4][4], b[2][4][2];
            // prologue: frags for s=0
            #pragma unroll
            for (int np = 0; np < 2; ++np) {
                uint32_t r0, r1, r2, r3;
                asm volatile("ldmatrix.sync.aligned.m8n8.x4.shared.b16 "
                             "{%0,%1,%2,%3}, [%4];"
                             : "=r"(r0), "=r"(r1), "=r"(r2), "=r"(r3)
                             : "r"(bBuf + np * (16 * BROWB)));
                b[0][2 * np][0] = r0; b[0][2 * np][1] = r1;
                b[0][2 * np + 1][0] = r2; b[0][2 * np + 1][1] = r3;
            }
            #pragma unroll
            for (int mt = 0; mt < 4; ++mt)
                asm volatile("ldmatrix.sync.aligned.m8n8.x4.shared.b16 "
                             "{%0,%1,%2,%3}, [%4];"
                             : "=r"(a[0][mt][0]), "=r"(a[0][mt][1]),
                               "=r"(a[0][mt][2]), "=r"(a[0][mt][3])
                             : "r"(aCol + mt * (16 * ASTRIDE * 2)));

            #pragma unroll
            for (int s = 0; s < 4; ++s) {
                const int cur = s & 1, nxt = cur ^ 1;
                if (s < 3) {   // prefetch frags for s+1
                    #pragma unroll
                    for (int np = 0; np < 2; ++np) {
                        uint32_t r0, r1, r2, r3;
                        asm volatile("ldmatrix.sync.aligned.m8n8.x4.shared.b16 "
                                     "{%0,%1,%2,%3}, [%4];"
                                     : "=r"(r0), "=r"(r1), "=r"(r2), "=r"(r3)
                                     : "r"(bBuf + np * (16 * BROWB) + (s + 1) * 32));
                        b[nxt][2 * np][0] = r0; b[nxt][2 * np][1] = r1;
                        b[nxt][2 * np + 1][0] = r2; b[nxt][2 * np + 1][1] = r3;
                    }
                    #pragma unroll
                    for (int mt = 0; mt < 4; ++mt)
                        asm volatile("ldmatrix.sync.aligned.m8n8.x4.shared.b16 "
                                     "{%0,%1,%2,%3}, [%4];"
                                     : "=r"(a[nxt][mt][0]), "=r"(a[nxt][mt][1]),
                                       "=r"(a[nxt][mt][2]), "=r"(a[nxt][mt][3])
                                     : "r"(aCol + mt * (16 * ASTRIDE * 2)
                                           + (s + 1) * 32));
                }
                #pragma unroll
                for (int mt = 0; mt < 4; ++mt)
                    #pragma unroll
                    for (int nt = 0; nt < 4; ++nt) {
                        asm volatile(
                            "mma.sync.aligned.m16n8k16.row.col.f16.f16.f16.f16 "
                            "{%0,%1}, {%2,%3,%4,%5}, {%6,%7}, {%0,%1};"
                            : "+r"(acc[mt][nt][0]), "+r"(acc[mt][nt][1])
                            : "r"(a[cur][mt][0]), "r"(a[cur][mt][1]),
                              "r"(a[cur][mt][2]), "r"(a[cur][mt][3]),
                              "r"(b[cur][nt][0]), "r"(b[cur][nt][1]));
                    }
            }
        }

        // ---- fold tile into persistent row-min regs ----
        const int cb = mbase + t * TILE_N + wn * 32 + (lane & 3) * 2;
        #pragma unroll
        for (int nt = 0; nt < 4; ++nt) {
            float m0 = __ldg(&g_msq[cb + nt * 8]);
            float m1 = __ldg(&g_msq[cb + nt * 8 + 1]);
            #pragma unroll
            for (int mt = 0; mt < 4; ++mt) {
                float2 p0 = __half22float2(*(__half2*)&acc[mt][nt][0]);
                float2 p1 = __half22float2(*(__half2*)&acc[mt][nt][1]);
                float v0 = fmaf(-2.f, p0.x, m0);
                float v1 = fmaf(-2.f, p0.y, m1);
                float v2 = fmaf(-2.f, p1.x, m0);
                float v3 = fmaf(-2.f, p1.y, m1);
                rowmin[mt][0] = fminf(rowmin[mt][0], fminf(v0, v1));
                rowmin[mt][1] = fminf(rowmin[mt][1], fminf(v2, v3));
            }
        }
    }

    // ---- final reduction: lanes sharing rows, then across wn warps ----
    #pragma unroll
    for (int mt = 0; mt < 4; ++mt)
        #pragma unroll
        for (int h = 0; h < 2; ++h) {
            float v = rowmin[mt][h];
            v = fminf(v, __shfl_xor_sync(0xffffffffu, v, 1));
            v = fminf(v, __shfl_xor_sync(0xffffffffu, v, 2));
            rowmin[mt][h] = v;
        }
    asm volatile("cp.async.wait_group 0;");
    __syncthreads();
    float* red = (float*)Asm;      // [8 wn][128 rows], aliases A region
    if ((lane & 3) == 0) {
        #pragma unroll
        for (int mt = 0; mt < 4; ++mt)
            #pragma unroll
            for (int h = 0; h < 2; ++h) {
                int row = wm * 64 + mt * 16 + (lane >> 2) + h * 8;
                red[wn * 128 + row] = rowmin[mt][h];
            }
    }
    __syncthreads();
    if (tid < 128) {
        float v = red[tid];
        #pragma unroll
        for (int wq = 1; wq < 8; ++wq)
            v = fminf(v, red[wq * 128 + tid]);
        g_part[split * NPATCH + n0 + tid] = v;
    }
}

// ============================ finalize ============================
__global__ void finalize_kernel(float* __restrict__ out) {
    int n = blockIdx.x * blockDim.x + threadIdx.x;
    if (n >= NPATCH) return;
    float m = fminf(g_part[n], fminf(g_part[NPATCH + n], g_part[2 * NPATCH + n]));
    float d2 = g_xsq[n] + m;
    d2 = fmaxf(d2, 1e-12f);
    out[n] = sqrtf(d2);
}

__global__ void img_max_kernel(float* __restrict__ out) {
    __shared__ float red[8];
    int b = blockIdx.x;
    int tid = threadIdx.x;
    float v = -3.0e38f;
    for (int i = tid; i < HDIM * WDIM; i += blockDim.x)
        v = fmaxf(v, out[b * (HDIM * WDIM) + i]);
    #pragma unroll
    for (int off = 16; off; off >>= 1)
        v = fmaxf(v, __shfl_xor_sync(0xffffffffu, v, off));
    if ((tid & 31) == 0) red[tid >> 5] = v;
    __syncthreads();
    if (tid < 8) {
        v = red[tid];
        #pragma unroll
        for (int off = 4; off; off >>= 1)
            v = fmaxf(v, __shfl_xor_sync(0x000000ffu, v, off));
        if (tid == 0) out[NPATCH + b] = v;
    }
}

// ============================ launch ============================
extern "C" void kernel_launch(void* const* d_in, const int* in_sizes, int n_in,
                              void* d_out, int out_size) {
    const float* f2   = (const float*)d_in[0];
    const float* f3   = (const float*)d_in[1];
    const float* bank = (const float*)d_in[2];
    float* out = (float*)d_out;

    cudaFuncSetAttribute(nn_kernel,
                         cudaFuncAttributeMaxDynamicSharedMemorySize, SM_TOTAL);

    embed_kernel<<<(NPATCH * CDIM + 255) / 256, 256>>>(f2, f3);
    bankcvt_kernel<<<(MBANK_PAD * 32 + 255) / 256, 256>>>(bank);
    xsq_kernel<<<(NPATCH * 32 + 255) / 256, 256>>>();

    dim3 grid(NTILES, MSPLIT);
    nn_kernel<<<grid, NTHREADS, SM_TOTAL>>>();

    finalize_kernel<<<(NPATCH + 255) / 256, 256>>>(out);
    if (out_size >= NPATCH + BATCH)
        img_max_kernel<<<BATCH, 256>>>(out);
}

// round 7
// speedup vs baseline: 1.3255x; 1.3255x over previous
#include <cuda_runtime.h>
#include <cuda_bf16.h>
#include <cstdint>

// ---------------- problem constants ----------------
#define BATCH   8
#define C2DIM   128
#define C3DIM   256
#define HDIM    28
#define WDIM    28
#define H3      14
#define W3      14
#define CDIM    384
#define NPATCH  6272
#define MBANK   30000
#define MBANK_PAD 30720             // 3 splits * 40 tiles * 256 rows

// ---------------- tiling ----------------
#define MSPLIT   3
#define TILE_M   128                // patches per CTA
#define TILE_N   256                // bank rows per CTA tile
#define NTILES   49                 // NPATCH / TILE_M
#define BTILES   40                 // bank tiles per split (40*256 = 10240)
#define CHUNKS   (BTILES * 6)       // k-chunks of 64 per split stream

#define ASTRIDE  392                // bf16 elems per A row (384 + 8 pad)
#define ABYTES   (128 * ASTRIDE * 2)    // 100352
#define BROWB    144                // bytes per B row (64 bf16 + 8 pad)
#define NSTAGE   3
#define PAIRSTG  (32 * BROWB)       // 4608 bytes: one pair-stage (32 rows x 64 cols)
#define PAIRB    (NSTAGE * PAIRSTG) // 13824 per pair
#define SM_TOTAL (ABYTES + 8 * PAIRB)   // 210944

#define NTHREADS 512

// ---------------- scratch ----------------
__device__ __align__(16) __nv_bfloat16 g_pat_bf[(size_t)NPATCH * CDIM];
__device__ __align__(16) __nv_bfloat16 g_bank_bf[(size_t)MBANK_PAD * CDIM];
__device__ float g_xsq[NPATCH];
__device__ float g_msq[MBANK_PAD];
__device__ float g_part[MSPLIT * NPATCH];

__device__ __forceinline__ uint32_t s2u(const void* p) {
    uint32_t r;
    asm("{ .reg .u64 t; cvta.to.shared.u64 t, %1; cvt.u32.u64 %0, t; }"
        : "=r"(r) : "l"(p));
    return r;
}

// ============================ prep kernels ============================
__global__ void embed_kernel(const float* __restrict__ f2,
                             const float* __restrict__ f3) {
    int idx = blockIdx.x * blockDim.x + threadIdx.x;
    if (idx >= NPATCH * CDIM) return;
    int n = idx / CDIM;
    int c = idx - n * CDIM;
    int b = n / (HDIM * WDIM);
    int hw = n - b * (HDIM * WDIM);
    int h = hw / WDIM;
    int w = hw - h * WDIM;

    float val;
    if (c < C2DIM) {
        val = f2[(((size_t)b * C2DIM + c) * HDIM + h) * WDIM + w];
    } else {
        int c3 = c - C2DIM;
        float sh = h * 0.5f - 0.25f;
        float sw = w * 0.5f - 0.25f;
        int h0 = (int)floorf(sh);
        int w0 = (int)floorf(sw);
        float th = sh - (float)h0;
        float tw = sw - (float)w0;
        int h0c = h0 < 0 ? 0 : h0;   int h1c = h0 + 1 > H3 - 1 ? H3 - 1 : h0 + 1;
        int w0c = w0 < 0 ? 0 : w0;   int w1c = w0 + 1 > W3 - 1 ? W3 - 1 : w0 + 1;
        const float* base = f3 + ((size_t)b * C3DIM + c3) * (H3 * W3);
        float v00 = base[h0c * W3 + w0c];
        float v01 = base[h0c * W3 + w1c];
        float v10 = base[h1c * W3 + w0c];
        float v11 = base[h1c * W3 + w1c];
        val = (1.f - th) * ((1.f - tw) * v00 + tw * v01)
            +        th  * ((1.f - tw) * v10 + tw * v11);
    }
    g_pat_bf[(size_t)n * CDIM + c] = __float2bfloat16(val);
}

// bank fp32 -> bf16 (+ zero pad rows) + squared norm of rounded values
__global__ void bankcvt_kernel(const float* __restrict__ bank) {
    int warp = (blockIdx.x * blockDim.x + threadIdx.x) >> 5;
    int lane = threadIdx.x & 31;
    if (warp >= MBANK_PAD) return;
    uint32_t* dst = (uint32_t*)(g_bank_bf + (size_t)warp * CDIM);
    if (warp >= MBANK) {
        #pragma unroll
        for (int j = 0; j < CDIM / 64; ++j) dst[j * 32 + lane] = 0u;
        if (lane == 0) g_msq[warp] = __int_as_float(0x7f800000);
        return;
    }
    const float2* src = (const float2*)(bank + (size_t)warp * CDIM);
    float s = 0.f;
    #pragma unroll
    for (int j = 0; j < CDIM / 64; ++j) {
        float2 v = src[j * 32 + lane];
        __nv_bfloat162 bv = __float22bfloat162_rn(v);
        dst[j * 32 + lane] = *(uint32_t*)&bv;
        float f0 = __bfloat162float(bv.x), f1 = __bfloat162float(bv.y);
        s += f0 * f0 + f1 * f1;
    }
    #pragma unroll
    for (int off = 16; off; off >>= 1) s += __shfl_xor_sync(0xffffffffu, s, off);
    if (lane == 0) g_msq[warp] = s;
}

__global__ void xsq_kernel() {
    int warp = (blockIdx.x * blockDim.x + threadIdx.x) >> 5;
    int lane = threadIdx.x & 31;
    if (warp >= NPATCH) return;
    const uint32_t* src = (const uint32_t*)(g_pat_bf + (size_t)warp * CDIM);
    float s = 0.f;
    #pragma unroll
    for (int j = 0; j < CDIM / 64; ++j) {
        uint32_t u = src[j * 32 + lane];
        __nv_bfloat162 bv = *(__nv_bfloat162*)&u;
        float f0 = __bfloat162float(bv.x), f1 = __bfloat162float(bv.y);
        s += f0 * f0 + f1 * f1;
    }
    #pragma unroll
    for (int off = 16; off; off >>= 1) s += __shfl_xor_sync(0xffffffffu, s, off);
    if (lane == 0) g_xsq[warp] = s;
}

// ============================ main GEMM+min kernel ============================
// 512 threads, 16 warps in 2(m) x 8(n); warp tile 64x32, mma.m16n8k16 bf16.
// Warp-pair (wm0,wm1 of same wn) shares a private B slice; no block barrier in
// the main loop — pairs sync via named bar.sync (wn+1), 64.
__global__ void __launch_bounds__(NTHREADS, 1) nn_kernel() {
    extern __shared__ __align__(1024) char smem[];
    char* Asm = smem;
    const int tid  = threadIdx.x;
    const int lane = tid & 31;
    const int wid  = tid >> 5;
    const int wm   = wid >> 3;      // 0..1
    const int wn   = wid & 7;       // 0..7
    const int n0   = blockIdx.x * TILE_M;
    const int split = blockIdx.y;
    const int mbase = split * (BTILES * TILE_N);

    const uint32_t aSm = s2u(smem);
    const uint32_t bSm = aSm + ABYTES + (uint32_t)wn * PAIRB;   // this pair's region

    // ---- load A tile (128 x 384 bf16) into smem, stride 392 ----
    #pragma unroll
    for (int i = 0; i < 12; ++i) {
        int e = i * NTHREADS + tid;
        int r = e / 48, q = e - r * 48;
        uint4 v = *(const uint4*)(g_pat_bf + (size_t)(n0 + r) * CDIM + q * 8);
        *(uint4*)(Asm + r * (ASTRIDE * 2) + q * 16) = v;
    }

    // per-lane ldmatrix base addresses
    const uint32_t aBase = aSm +
        ((wm * 64 + (lane & 15)) * ASTRIDE + (lane >> 4) * 8) * 2;
    const int lq = lane >> 3;
    const int bn = (lane & 7) + ((lq >> 1) << 3);    // local row 0..15
    const int bk = (lq & 1) << 3;
    const uint32_t bBase = bSm + bn * BROWB + bk * 2;

    float rowmin[4][2];
    #pragma unroll
    for (int i = 0; i < 4; ++i) {
        rowmin[i][0] = __int_as_float(0x7f800000);
        rowmin[i][1] = __int_as_float(0x7f800000);
    }

    // ---- pair chunk loader: 32 rows x 64 k-cols bf16 = 4KB, 2 warps split ----
    const int l64 = wm * 32 + lane;   // 0..63 within the pair
    auto load_chunk = [&](int cg) {
        int t  = cg / 6;
        int kc = cg - t * 6;
        int st = cg % NSTAGE;
        const char* src0 = (const char*)(g_bank_bf +
                           (size_t)(mbase + t * TILE_N + wn * 32) * CDIM + kc * 64);
        uint32_t dbase = bSm + (uint32_t)st * PAIRSTG;
        #pragma unroll
        for (int i = 0; i < 4; ++i) {
            int e = i * 64 + l64;
            int r = e >> 3, q = e & 7;
            uint32_t d = dbase + r * BROWB + q * 16;
            const char* s = src0 + (size_t)r * (CDIM * 2) + q * 16;
            asm volatile("cp.async.cg.shared.global [%0], [%1], 16;"
                         :: "r"(d), "l"(s));
        }
        asm volatile("cp.async.commit_group;");
    };

    load_chunk(0);
    load_chunk(1);
    __syncthreads();   // covers A-tile stores (and everyone's first loads issued)

    const int barid = wn + 1;
    int cg = 0;
    for (int t = 0; t < BTILES; ++t) {
        float acc[4][4][4];
        #pragma unroll
        for (int mt = 0; mt < 4; ++mt)
            #pragma unroll
            for (int nt = 0; nt < 4; ++nt)
                #pragma unroll
                for (int e = 0; e < 4; ++e) acc[mt][nt][e] = 0.f;

        #pragma unroll 1
        for (int j = 0; j < 6; ++j, ++cg) {
            asm volatile("cp.async.wait_group 1;");   // own chunk cg resident
            asm volatile("bar.sync %0, 64;" :: "r"(barid) : "memory"); // pair sync
            if (cg + 2 < CHUNKS) load_chunk(cg + 2);  // stage (cg+2)%3 free now

            const uint32_t bBuf = bBase + (uint32_t)(cg % NSTAGE) * PAIRSTG;
            #pragma unroll
            for (int s = 0; s < 4; ++s) {
                // B frags: 2 x4-ldmatrix -> 4 n8-tiles x {b0,b1}
                uint32_t b[4][2];
                #pragma unroll
                for (int np = 0; np < 2; ++np) {
                    uint32_t r0, r1, r2, r3;
                    uint32_t ad = bBuf + np * (16 * BROWB) + s * 32;
                    asm volatile(
                        "ldmatrix.sync.aligned.m8n8.x4.shared.b16 "
                        "{%0,%1,%2,%3}, [%4];"
                        : "=r"(r0), "=r"(r1), "=r"(r2), "=r"(r3) : "r"(ad));
                    b[2 * np][0] = r0; b[2 * np][1] = r1;
                    b[2 * np + 1][0] = r2; b[2 * np + 1][1] = r3;
                }
                // A frags: 4 x4-ldmatrix -> 4 m16-tiles x {a0..a3}
                uint32_t a[4][4];
                #pragma unroll
                for (int mt = 0; mt < 4; ++mt) {
                    uint32_t ad = aBase + mt * (16 * ASTRIDE * 2)
                                + (j * 64 + s * 16) * 2;
                    asm volatile(
                        "ldmatrix.sync.aligned.m8n8.x4.shared.b16 "
                        "{%0,%1,%2,%3}, [%4];"
                        : "=r"(a[mt][0]), "=r"(a[mt][1]),
                          "=r"(a[mt][2]), "=r"(a[mt][3]) : "r"(ad));
                }
                #pragma unroll
                for (int mt = 0; mt < 4; ++mt)
                    #pragma unroll
                    for (int nt = 0; nt < 4; ++nt) {
                        asm volatile(
                            "mma.sync.aligned.m16n8k16.row.col.f32.bf16.bf16.f32 "
                            "{%0,%1,%2,%3}, {%4,%5,%6,%7}, {%8,%9}, {%0,%1,%2,%3};"
                            : "+f"(acc[mt][nt][0]), "+f"(acc[mt][nt][1]),
                              "+f"(acc[mt][nt][2]), "+f"(acc[mt][nt][3])
                            : "r"(a[mt][0]), "r"(a[mt][1]),
                              "r"(a[mt][2]), "r"(a[mt][3]),
                              "r"(b[nt][0]), "r"(b[nt][1]));
                    }
            }
        }

        // ---- fold tile into persistent row-min regs ----
        const int cb = mbase + t * TILE_N + wn * 32 + (lane & 3) * 2;
        #pragma unroll
        for (int nt = 0; nt < 4; ++nt) {
            float m0 = __ldg(&g_msq[cb + nt * 8]);
            float m1 = __ldg(&g_msq[cb + nt * 8 + 1]);
            #pragma unroll
            for (int mt = 0; mt < 4; ++mt) {
                float v0 = fmaf(-2.f, acc[mt][nt][0], m0);
                float v1 = fmaf(-2.f, acc[mt][nt][1], m1);
                float v2 = fmaf(-2.f, acc[mt][nt][2], m0);
                float v3 = fmaf(-2.f, acc[mt][nt][3], m1);
                rowmin[mt][0] = fminf(rowmin[mt][0], fminf(v0, v1));
                rowmin[mt][1] = fminf(rowmin[mt][1], fminf(v2, v3));
            }
        }
    }

    // ---- final reduction: lanes sharing rows, then across wn warps ----
    #pragma unroll
    for (int mt = 0; mt < 4; ++mt)
        #pragma unroll
        for (int h = 0; h < 2; ++h) {
            float v = rowmin[mt][h];
            v = fminf(v, __shfl_xor_sync(0xffffffffu, v, 1));
            v = fminf(v, __shfl_xor_sync(0xffffffffu, v, 2));
            rowmin[mt][h] = v;
        }
    asm volatile("cp.async.wait_group 0;");
    __syncthreads();
    float* red = (float*)Asm;      // [8 wn][128 rows], aliases A region
    if ((lane & 3) == 0) {
        #pragma unroll
        for (int mt = 0; mt < 4; ++mt)
            #pragma unroll
            for (int h = 0; h < 2; ++h) {
                int row = wm * 64 + mt * 16 + (lane >> 2) + h * 8;
                red[wn * 128 + row] = rowmin[mt][h];
            }
    }
    __syncthreads();
    if (tid < 128) {
        float v = red[tid];
        #pragma unroll
        for (int wq = 1; wq < 8; ++wq)
            v = fminf(v, red[wq * 128 + tid]);
        g_part[split * NPATCH + n0 + tid] = v;
    }
}

// ============================ finalize ============================
__global__ void finalize_kernel(float* __restrict__ out) {
    int n = blockIdx.x * blockDim.x + threadIdx.x;
    if (n >= NPATCH) return;
    float m = fminf(g_part[n], fminf(g_part[NPATCH + n], g_part[2 * NPATCH + n]));
    float d2 = g_xsq[n] + m;
    d2 = fmaxf(d2, 1e-12f);
    out[n] = sqrtf(d2);
}

__global__ void img_max_kernel(float* __restrict__ out) {
    __shared__ float red[8];
    int b = blockIdx.x;
    int tid = threadIdx.x;
    float v = -3.0e38f;
    for (int i = tid; i < HDIM * WDIM; i += blockDim.x)
        v = fmaxf(v, out[b * (HDIM * WDIM) + i]);
    #pragma unroll
    for (int off = 16; off; off >>= 1)
        v = fmaxf(v, __shfl_xor_sync(0xffffffffu, v, off));
    if ((tid & 31) == 0) red[tid >> 5] = v;
    __syncthreads();
    if (tid < 8) {
        v = red[tid];
        #pragma unroll
        for (int off = 4; off; off >>= 1)
            v = fmaxf(v, __shfl_xor_sync(0x000000ffu, v, off));
        if (tid == 0) out[NPATCH + b] = v;
    }
}

// ============================ launch ============================
extern "C" void kernel_launch(void* const* d_in, const int* in_sizes, int n_in,
                              void* d_out, int out_size) {
    const float* f2   = (const float*)d_in[0];
    const float* f3   = (const float*)d_in[1];
    const float* bank = (const float*)d_in[2];
    float* out = (float*)d_out;

    cudaFuncSetAttribute(nn_kernel,
                         cudaFuncAttributeMaxDynamicSharedMemorySize, SM_TOTAL);

    embed_kernel<<<(NPATCH * CDIM + 255) / 256, 256>>>(f2, f3);
    bankcvt_kernel<<<(MBANK_PAD * 32 + 255) / 256, 256>>>(bank);
    xsq_kernel<<<(NPATCH * 32 + 255) / 256, 256>>>();

    dim3 grid(NTILES, MSPLIT);
    nn_kernel<<<grid, NTHREADS, SM_TOTAL>>>();

    finalize_kernel<<<(NPATCH + 255) / 256, 256>>>(out);
    if (out_size >= NPATCH + BATCH)
        img_max_kernel<<<BATCH, 256>>>(out);
}

// round 8
// speedup vs baseline: 1.3950x; 1.0525x over previous
#include <cuda_runtime.h>
#include <cuda_bf16.h>
#include <cstdint>

// ---------------- problem constants ----------------
#define BATCH   8
#define C2DIM   128
#define C3DIM   256
#define HDIM    28
#define WDIM    28
#define H3      14
#define W3      14
#define CDIM    384
#define NPATCH  6272
#define MBANK   30000
#define MBANK_PAD 30720             // 3 splits * 40 tiles * 256 rows

// ---------------- tiling ----------------
#define MSPLIT   3
#define TILE_M   128                // patches per CTA
#define TILE_N   256                // bank rows per CTA tile
#define NTILES   49                 // NPATCH / TILE_M
#define BTILES   40                 // bank tiles per split (40*256 = 10240)

#define ASTRIDE  392                // bf16 elems per A row (384 + 8 pad)
#define ABYTES   (128 * ASTRIDE * 2)    // 100352
#define BROWB    144                // bytes per B row (64 bf16 + 8 pad)
#define NSTAGE   3
#define PAIRSTG  (32 * BROWB)       // 4608 bytes: one pair-stage (32 rows x 64 cols)
#define PAIRB    (NSTAGE * PAIRSTG) // 13824 per pair
#define SM_TOTAL (ABYTES + 8 * PAIRB)   // 210944

#define NTHREADS 512
#define TILEBYTES ((size_t)TILE_N * CDIM * 2)   // gmem bytes per bank tile row-block

// ---------------- scratch ----------------
__device__ __align__(16) __nv_bfloat16 g_pat_bf[(size_t)NPATCH * CDIM];
__device__ __align__(16) __nv_bfloat16 g_bank_bf[(size_t)MBANK_PAD * CDIM];
__device__ float g_xsq[NPATCH];
__device__ float g_msq[MBANK_PAD];
__device__ float g_part[MSPLIT * NPATCH];

__device__ __forceinline__ uint32_t s2u(const void* p) {
    uint32_t r;
    asm("{ .reg .u64 t; cvta.to.shared.u64 t, %1; cvt.u32.u64 %0, t; }"
        : "=r"(r) : "l"(p));
    return r;
}

// ============================ prep kernels ============================
__global__ void embed_kernel(const float* __restrict__ f2,
                             const float* __restrict__ f3) {
    int idx = blockIdx.x * blockDim.x + threadIdx.x;
    if (idx >= NPATCH * CDIM) return;
    int n = idx / CDIM;
    int c = idx - n * CDIM;
    int b = n / (HDIM * WDIM);
    int hw = n - b * (HDIM * WDIM);
    int h = hw / WDIM;
    int w = hw - h * WDIM;

    float val;
    if (c < C2DIM) {
        val = f2[(((size_t)b * C2DIM + c) * HDIM + h) * WDIM + w];
    } else {
        int c3 = c - C2DIM;
        float sh = h * 0.5f - 0.25f;
        float sw = w * 0.5f - 0.25f;
        int h0 = (int)floorf(sh);
        int w0 = (int)floorf(sw);
        float th = sh - (float)h0;
        float tw = sw - (float)w0;
        int h0c = h0 < 0 ? 0 : h0;   int h1c = h0 + 1 > H3 - 1 ? H3 - 1 : h0 + 1;
        int w0c = w0 < 0 ? 0 : w0;   int w1c = w0 + 1 > W3 - 1 ? W3 - 1 : w0 + 1;
        const float* base = f3 + ((size_t)b * C3DIM + c3) * (H3 * W3);
        float v00 = base[h0c * W3 + w0c];
        float v01 = base[h0c * W3 + w1c];
        float v10 = base[h1c * W3 + w0c];
        float v11 = base[h1c * W3 + w1c];
        val = (1.f - th) * ((1.f - tw) * v00 + tw * v01)
            +        th  * ((1.f - tw) * v10 + tw * v11);
    }
    g_pat_bf[(size_t)n * CDIM + c] = __float2bfloat16(val);
}

// bank fp32 -> bf16 (+ zero pad rows) + squared norm of rounded values
__global__ void bankcvt_kernel(const float* __restrict__ bank) {
    int warp = (blockIdx.x * blockDim.x + threadIdx.x) >> 5;
    int lane = threadIdx.x & 31;
    if (warp >= MBANK_PAD) return;
    uint32_t* dst = (uint32_t*)(g_bank_bf + (size_t)warp * CDIM);
    if (warp >= MBANK) {
        #pragma unroll
        for (int j = 0; j < CDIM / 64; ++j) dst[j * 32 + lane] = 0u;
        if (lane == 0) g_msq[warp] = __int_as_float(0x7f800000);
        return;
    }
    const float2* src = (const float2*)(bank + (size_t)warp * CDIM);
    float s = 0.f;
    #pragma unroll
    for (int j = 0; j < CDIM / 64; ++j) {
        float2 v = src[j * 32 + lane];
        __nv_bfloat162 bv = __float22bfloat162_rn(v);
        dst[j * 32 + lane] = *(uint32_t*)&bv;
        float f0 = __bfloat162float(bv.x), f1 = __bfloat162float(bv.y);
        s += f0 * f0 + f1 * f1;
    }
    #pragma unroll
    for (int off = 16; off; off >>= 1) s += __shfl_xor_sync(0xffffffffu, s, off);
    if (lane == 0) g_msq[warp] = s;
}

__global__ void xsq_kernel() {
    int warp = (blockIdx.x * blockDim.x + threadIdx.x) >> 5;
    int lane = threadIdx.x & 31;
    if (warp >= NPATCH) return;
    const uint32_t* src = (const uint32_t*)(g_pat_bf + (size_t)warp * CDIM);
    float s = 0.f;
    #pragma unroll
    for (int j = 0; j < CDIM / 64; ++j) {
        uint32_t u = src[j * 32 + lane];
        __nv_bfloat162 bv = *(__nv_bfloat162*)&u;
        float f0 = __bfloat162float(bv.x), f1 = __bfloat162float(bv.y);
        s += f0 * f0 + f1 * f1;
    }
    #pragma unroll
    for (int off = 16; off; off >>= 1) s += __shfl_xor_sync(0xffffffffu, s, off);
    if (lane == 0) g_xsq[warp] = s;
}

// ============================ main GEMM+min kernel ============================
// 512 threads, 16 warps in 2(m) x 8(n); warp tile 64x32, mma.m16n8k16 bf16.
// Warp-pair (wm0,wm1 of same wn) shares a private 3-stage B ring; pairs sync
// with named bar.sync. j-loop fully unrolled: 6 chunks/tile, 3 stages, 6%3==0
// so every tile starts at stage 0 -> all stage indices & addresses are
// compile-time constants.
__global__ void __launch_bounds__(NTHREADS, 1) nn_kernel() {
    extern __shared__ __align__(1024) char smem[];
    char* Asm = smem;
    const int tid  = threadIdx.x;
    const int lane = tid & 31;
    const int wid  = tid >> 5;
    const int wm   = wid >> 3;      // 0..1
    const int wn   = wid & 7;       // 0..7
    const int n0   = blockIdx.x * TILE_M;
    const int split = blockIdx.y;
    const int mbase = split * (BTILES * TILE_N);

    const uint32_t aSm = s2u(smem);
    const uint32_t bSm = aSm + ABYTES + (uint32_t)wn * PAIRB;   // pair region

    // ---- load A tile (128 x 384 bf16) into smem, stride 392 ----
    #pragma unroll
    for (int i = 0; i < 12; ++i) {
        int e = i * NTHREADS + tid;
        int r = e / 48, q = e - r * 48;
        uint4 v = *(const uint4*)(g_pat_bf + (size_t)(n0 + r) * CDIM + q * 8);
        *(uint4*)(Asm + r * (ASTRIDE * 2) + q * 16) = v;
    }

    // per-lane ldmatrix base addresses
    const uint32_t aBase = aSm +
        ((wm * 64 + (lane & 15)) * ASTRIDE + (lane >> 4) * 8) * 2;
    const int lq = lane >> 3;
    const int bn = (lane & 7) + ((lq >> 1) << 3);    // local row 0..15
    const int bk = (lq & 1) << 3;
    const uint32_t bBase = bSm + bn * BROWB + bk * 2;

    float rowmin[4][2];
    #pragma unroll
    for (int i = 0; i < 4; ++i) {
        rowmin[i][0] = __int_as_float(0x7f800000);
        rowmin[i][1] = __int_as_float(0x7f800000);
    }

    // ---- pair chunk loader: 32 rows x 64 k-cols bf16 = 4KB, 2 warps split ----
    const int l64 = wm * 32 + lane;   // 0..63 within the pair
    const int lr = l64 >> 3, lqq = l64 & 7;   // each thread: 4 rows x 1 quad
    auto load_at = [&](const char* src0, uint32_t dbase) {
        #pragma unroll
        for (int i = 0; i < 4; ++i) {
            int r = lr + i * 8;
            uint32_t d = dbase + r * BROWB + lqq * 16;
            const char* s = src0 + (size_t)r * (CDIM * 2) + lqq * 16;
            asm volatile("cp.async.cg.shared.global [%0], [%1], 16;"
                         :: "r"(d), "l"(s));
        }
        asm volatile("cp.async.commit_group;");
    };

    // pair's gmem base for tile 0
    const char* tileSrc = (const char*)(g_bank_bf +
                          (size_t)(mbase + wn * 32) * CDIM);

    load_at(tileSrc + 0 * 128, bSm + 0 * PAIRSTG);   // chunk 0 -> stage 0
    load_at(tileSrc + 1 * 128, bSm + 1 * PAIRSTG);   // chunk 1 -> stage 1
    __syncthreads();   // covers A-tile stores

    const int barid = wn + 1;
    for (int t = 0; t < BTILES; ++t) {
        float acc[4][4][4];
        #pragma unroll
        for (int mt = 0; mt < 4; ++mt)
            #pragma unroll
            for (int nt = 0; nt < 4; ++nt)
                #pragma unroll
                for (int e = 0; e < 4; ++e) acc[mt][nt][e] = 0.f;

        const bool more = (t + 1) < BTILES;
        const char* nextSrc = tileSrc + TILEBYTES;

        #pragma unroll
        for (int j = 0; j < 6; ++j) {
            asm volatile("cp.async.wait_group 1;");   // own chunk j resident
            asm volatile("bar.sync %0, 64;" :: "r"(barid) : "memory");
            // load chunk j+2 into stage (j+2)%3
            if (j < 4) {
                load_at(tileSrc + (j + 2) * 128,
                        bSm + (uint32_t)(((j + 2) % 3) * PAIRSTG));
            } else if (more) {
                load_at(nextSrc + (j - 4) * 128,
                        bSm + (uint32_t)(((j + 2) % 3) * PAIRSTG));
            } else {
                asm volatile("cp.async.commit_group;");  // keep group count in sync
            }

            const uint32_t bBuf = bBase + (uint32_t)((j % 3) * PAIRSTG);
            #pragma unroll
            for (int s = 0; s < 4; ++s) {
                // B frags first (feed all 16 MMAs): 2 x4-ldmatrix -> 4 n8-tiles
                uint32_t b[4][2];
                #pragma unroll
                for (int np = 0; np < 2; ++np) {
                    uint32_t r0, r1, r2, r3;
                    uint32_t ad = bBuf + np * (16 * BROWB) + s * 32;
                    asm volatile(
                        "ldmatrix.sync.aligned.m8n8.x4.shared.b16 "
                        "{%0,%1,%2,%3}, [%4];"
                        : "=r"(r0), "=r"(r1), "=r"(r2), "=r"(r3) : "r"(ad));
                    b[2 * np][0] = r0; b[2 * np][1] = r1;
                    b[2 * np + 1][0] = r2; b[2 * np + 1][1] = r3;
                }
                // A frags: 4 x4-ldmatrix -> 4 m16-tiles x {a0..a3}
                uint32_t a[4][4];
                #pragma unroll
                for (int mt = 0; mt < 4; ++mt) {
                    uint32_t ad = aBase + mt * (16 * ASTRIDE * 2)
                                + (j * 64 + s * 16) * 2;
                    asm volatile(
                        "ldmatrix.sync.aligned.m8n8.x4.shared.b16 "
                        "{%0,%1,%2,%3}, [%4];"
                        : "=r"(a[mt][0]), "=r"(a[mt][1]),
                          "=r"(a[mt][2]), "=r"(a[mt][3]) : "r"(ad));
                }
                #pragma unroll
                for (int mt = 0; mt < 4; ++mt)
                    #pragma unroll
                    for (int nt = 0; nt < 4; ++nt) {
                        asm volatile(
                            "mma.sync.aligned.m16n8k16.row.col.f32.bf16.bf16.f32 "
                            "{%0,%1,%2,%3}, {%4,%5,%6,%7}, {%8,%9}, {%0,%1,%2,%3};"
                            : "+f"(acc[mt][nt][0]), "+f"(acc[mt][nt][1]),
                              "+f"(acc[mt][nt][2]), "+f"(acc[mt][nt][3])
                            : "r"(a[mt][0]), "r"(a[mt][1]),
                              "r"(a[mt][2]), "r"(a[mt][3]),
                              "r"(b[nt][0]), "r"(b[nt][1]));
                    }
            }
        }
        tileSrc = nextSrc;

        // ---- fold tile into persistent row-min regs ----
        const int cb = mbase + t * TILE_N + wn * 32 + (lane & 3) * 2;
        #pragma unroll
        for (int nt = 0; nt < 4; ++nt) {
            float m0 = __ldg(&g_msq[cb + nt * 8]);
            float m1 = __ldg(&g_msq[cb + nt * 8 + 1]);
            #pragma unroll
            for (int mt = 0; mt < 4; ++mt) {
                float v0 = fmaf(-2.f, acc[mt][nt][0], m0);
                float v1 = fmaf(-2.f, acc[mt][nt][1], m1);
                float v2 = fmaf(-2.f, acc[mt][nt][2], m0);
                float v3 = fmaf(-2.f, acc[mt][nt][3], m1);
                rowmin[mt][0] = fminf(rowmin[mt][0], fminf(v0, v1));
                rowmin[mt][1] = fminf(rowmin[mt][1], fminf(v2, v3));
            }
        }
    }

    // ---- final reduction: lanes sharing rows, then across wn warps ----
    #pragma unroll
    for (int mt = 0; mt < 4; ++mt)
        #pragma unroll
        for (int h = 0; h < 2; ++h) {
            float v = rowmin[mt][h];
            v = fminf(v, __shfl_xor_sync(0xffffffffu, v, 1));
            v = fminf(v, __shfl_xor_sync(0xffffffffu, v, 2));
            rowmin[mt][h] = v;
        }
    asm volatile("cp.async.wait_group 0;");
    __syncthreads();
    float* red = (float*)Asm;      // [8 wn][128 rows], aliases A region
    if ((lane & 3) == 0) {
        #pragma unroll
        for (int mt = 0; mt < 4; ++mt)
            #pragma unroll
            for (int h = 0; h < 2; ++h) {
                int row = wm * 64 + mt * 16 + (lane >> 2) + h * 8;
                red[wn * 128 + row] = rowmin[mt][h];
            }
    }
    __syncthreads();
    if (tid < 128) {
        float v = red[tid];
        #pragma unroll
        for (int wq = 1; wq < 8; ++wq)
            v = fminf(v, red[wq * 128 + tid]);
        g_part[split * NPATCH + n0 + tid] = v;
    }
}

// ============================ finalize ============================
__global__ void finalize_kernel(float* __restrict__ out) {
    int n = blockIdx.x * blockDim.x + threadIdx.x;
    if (n >= NPATCH) return;
    float m = fminf(g_part[n], fminf(g_part[NPATCH + n], g_part[2 * NPATCH + n]));
    float d2 = g_xsq[n] + m;
    d2 = fmaxf(d2, 1e-12f);
    out[n] = sqrtf(d2);
}

__global__ void img_max_kernel(float* __restrict__ out) {
    __shared__ float red[8];
    int b = blockIdx.x;
    int tid = threadIdx.x;
    float v = -3.0e38f;
    for (int i = tid; i < HDIM * WDIM; i += blockDim.x)
        v = fmaxf(v, out[b * (HDIM * WDIM) + i]);
    #pragma unroll
    for (int off = 16; off; off >>= 1)
        v = fmaxf(v, __shfl_xor_sync(0xffffffffu, v, off));
    if ((tid & 31) == 0) red[tid >> 5] = v;
    __syncthreads();
    if (tid < 8) {
        v = red[tid];
        #pragma unroll
        for (int off = 4; off; off >>= 1)
            v = fmaxf(v, __shfl_xor_sync(0x000000ffu, v, off));
        if (tid == 0) out[NPATCH + b] = v;
    }
}

// ============================ launch ============================
extern "C" void kernel_launch(void* const* d_in, const int* in_sizes, int n_in,
                              void* d_out, int out_size) {
    const float* f2   = (const float*)d_in[0];
    const float* f3   = (const float*)d_in[1];
    const float* bank = (const float*)d_in[2];
    float* out = (float*)d_out;

    cudaFuncSetAttribute(nn_kernel,
                         cudaFuncAttributeMaxDynamicSharedMemorySize, SM_TOTAL);

    embed_kernel<<<(NPATCH * CDIM + 255) / 256, 256>>>(f2, f3);
    bankcvt_kernel<<<(MBANK_PAD * 32 + 255) / 256, 256>>>(bank);
    xsq_kernel<<<(NPATCH * 32 + 255) / 256, 256>>>();

    dim3 grid(NTILES, MSPLIT);
    nn_kernel<<<grid, NTHREADS, SM_TOTAL>>>();

    finalize_kernel<<<(NPATCH + 255) / 256, 256>>>(out);
    if (out_size >= NPATCH + BATCH)
        img_max_kernel<<<BATCH, 256>>>(out);
}